// round 3
// baseline (speedup 1.0000x reference)
#include <cuda_runtime.h>
#include <cuda_fp16.h>
#include <cstdint>
#include <cstddef>

#define BATCH 8192
#define IN_F  1024
#define OUT_F 1024

// ---------------- scratch (static device globals; no allocation) ----------------
__device__ __align__(128) __half   g_x16[(size_t)BATCH * IN_F];  // fp16 x (16 MB)
__device__ __align__(128) __half   g_Ht[(size_t)OUT_F * IN_F];   // Ht[j][i] = H^T, [N][K] (2 MB)
__device__ __align__(16)  float    g_gbar[IN_F];                 // sum_j G_quant[i][j]
__device__ __align__(16)  float    g_geffbar[IN_F];              // sum_j G_eff[i][j]
__device__ float    g_corr[BATCH];
__device__ unsigned g_minmax[2];

// ---------------- small helpers ----------------
__device__ __forceinline__ unsigned fmap(float f) {
    unsigned u = __float_as_uint(f);
    return (u & 0x80000000u) ? ~u : (u | 0x80000000u);
}
__device__ __forceinline__ float funmap(unsigned m) {
    unsigned u = (m & 0x80000000u) ? (m ^ 0x80000000u) : ~m;
    return __uint_as_float(u);
}

__global__ void k_init() {
    int i = blockIdx.x * 256 + threadIdx.x;
    g_gbar[i] = 0.f;
    g_geffbar[i] = 0.f;
    if (i == 0) { g_minmax[0] = 0xFFFFFFFFu; g_minmax[1] = 0u; }
}

__global__ void k_minmax(const float* __restrict__ w, int n) {
    unsigned lmin = 0xFFFFFFFFu, lmax = 0u;
    for (int i = blockIdx.x * blockDim.x + threadIdx.x; i < n; i += gridDim.x * blockDim.x) {
        unsigned m = fmap(w[i]);
        lmin = min(lmin, m);
        lmax = max(lmax, m);
    }
#pragma unroll
    for (int o = 16; o; o >>= 1) {
        lmin = min(lmin, __shfl_xor_sync(0xFFFFFFFFu, lmin, o));
        lmax = max(lmax, __shfl_xor_sync(0xFFFFFFFFu, lmax, o));
    }
    __shared__ unsigned smin[8], smax[8];
    int warp = threadIdx.x >> 5;
    if ((threadIdx.x & 31) == 0) { smin[warp] = lmin; smax[warp] = lmax; }
    __syncthreads();
    if (threadIdx.x == 0) {
        unsigned a = smin[0], b = smax[0];
        for (int i = 1; i < 8; i++) { a = min(a, smin[i]); b = max(b, smax[i]); }
        atomicMin(&g_minmax[0], a);
        atomicMax(&g_minmax[1], b);
    }
}

// Build Ht[j][i] = ((G_eff - b)/a) in the SAME layout as weight (coalesced in i).
// Also accumulate per-i column sums of G_quant / G_eff (ratio of means == ratio of sums).
__global__ void k_build_ht(const float* __restrict__ w) {
    const int i  = blockIdx.x * 256 + threadIdx.x;   // input index (contiguous per warp)
    const int j0 = blockIdx.y * 128;                 // output-row chunk
    const float Wmin = funmap(g_minmax[0]);
    const float Wmax = funmap(g_minmax[1]);
    const float Ghrs = (float)(1.0 / 1000000.0);
    const float span = (float)(1.0 / 1000.0 - 1.0 / 1000000.0);
    const float step = (float)((1.0 / 1000.0 - 1.0 / 1000000.0) / 15.0);
    const float denomW = __fsub_rn(Wmax, Wmin);
    const float a      = __fdiv_rn(span, denomW);
    const float bconst = __fsub_rn(Ghrs, __fmul_rn(a, Wmin));
    const float rowterm = (float)(IN_F - i);

    float s_g = 0.f, s_e = 0.f;
#pragma unroll 4
    for (int jj = 0; jj < 128; jj++) {
        const int j = j0 + jj;
        float wv = w[(size_t)j * IN_F + i];
        float u  = __fdiv_rn(__fsub_rn(wv, Wmin), denomW);
        float G  = __fadd_rn(__fmul_rn(u, span), Ghrs);
        float q  = rintf(__fdiv_rn(__fsub_rn(G, Ghrs), step));
        float Gq = __fadd_rn(__fmul_rn(q, step), Ghrs);
        float rser = __fmul_rn(2.0f, __fadd_rn((float)(j + 1), rowterm));
        float Geff = __fdiv_rn(1.0f, __fadd_rn(__fdiv_rn(1.0f, Gq), rser));
        g_Ht[(size_t)j * IN_F + i] = __float2half_rn(__fdiv_rn(__fsub_rn(Geff, bconst), a));
        s_g += Gq;
        s_e += Geff;
    }
    atomicAdd(&g_gbar[i], s_g);
    atomicAdd(&g_geffbar[i], s_e);
}

// One block per batch row: convert x -> fp16 AND compute corr[b] in one pass (fp32 dots).
__global__ void k_convert_corr(const float4* __restrict__ x) {
    const int b = blockIdx.x;
    const int t = threadIdx.x;
    float4 v = x[(size_t)b * 256 + t];
    __half2* dst = reinterpret_cast<__half2*>(g_x16 + (size_t)b * IN_F);
    dst[2 * t]     = __floats2half2_rn(v.x, v.y);
    dst[2 * t + 1] = __floats2half2_rn(v.z, v.w);

    const float4 ge = reinterpret_cast<const float4*>(g_geffbar)[t];
    const float4 gb = reinterpret_cast<const float4*>(g_gbar)[t];
    float num = v.x * ge.x + v.y * ge.y + v.z * ge.z + v.w * ge.w;
    float den = v.x * gb.x + v.y * gb.y + v.z * gb.z + v.w * gb.w;
#pragma unroll
    for (int o = 16; o; o >>= 1) {
        num += __shfl_xor_sync(0xFFFFFFFFu, num, o);
        den += __shfl_xor_sync(0xFFFFFFFFu, den, o);
    }
    __shared__ float sn[8], sd[8];
    const int warp = t >> 5;
    if ((t & 31) == 0) { sn[warp] = num; sd[warp] = den; }
    __syncthreads();
    if (t == 0) {
        float n2 = sn[0], d2 = sd[0];
        for (int i = 1; i < 8; i++) { n2 += sn[i]; d2 += sd[i]; }
        g_corr[b] = n2 / d2;
    }
}

// ========== fp16 mma.sync GEMM: out = x16 @ Ht^T + bias*corr ==========
// BM=128, BN=128, BK=64, 256 threads (8 warps 4x2, warp tile 32x64), double buffered.
// A: [M][K] rows in smem; B: Ht [N][K] rows in smem -> both non-trans ldmatrix.

#define BK      64
#define LDS_ROW 72          // 64 + 8 halfs pad (16B) -> conflict-free ldmatrix phases
#define STAGE_HALFS (128 * LDS_ROW)
#define SMEM_DYN (2 * 2 * STAGE_HALFS * 2)   // 2 stages x (A+B) x halfs x 2B = 73728

__device__ __forceinline__ void cp16(void* smem, const void* g) {
    unsigned s = (unsigned)__cvta_generic_to_shared(smem);
    asm volatile("cp.async.cg.shared.global [%0], [%1], 16;\n" :: "r"(s), "l"(g));
}
__device__ __forceinline__ void ldm4(uint32_t* r, const void* p) {
    unsigned a = (unsigned)__cvta_generic_to_shared(p);
    asm volatile("ldmatrix.sync.aligned.m8n8.x4.shared.b16 {%0,%1,%2,%3}, [%4];\n"
                 : "=r"(r[0]), "=r"(r[1]), "=r"(r[2]), "=r"(r[3]) : "r"(a));
}
__device__ __forceinline__ void mma16816(float* d, const uint32_t* a, const uint32_t* b) {
    asm volatile("mma.sync.aligned.m16n8k16.row.col.f32.f16.f16.f32 "
                 "{%0,%1,%2,%3}, {%4,%5,%6,%7}, {%8,%9}, {%0,%1,%2,%3};\n"
                 : "+f"(d[0]), "+f"(d[1]), "+f"(d[2]), "+f"(d[3])
                 : "r"(a[0]), "r"(a[1]), "r"(a[2]), "r"(a[3]), "r"(b[0]), "r"(b[1]));
}

__global__ __launch_bounds__(256, 2) void k_gemm(const float* __restrict__ bias,
                                                 float* __restrict__ out) {
    extern __shared__ __align__(16) __half smem[];
    // layout: [stage][A(128x72) | B(128x72)]
    __half* As[2] = { smem,                     smem + 2 * STAGE_HALFS };
    __half* Bs[2] = { smem + STAGE_HALFS,       smem + 3 * STAGE_HALFS };

    const int bm = blockIdx.y * 128, bn = blockIdx.x * 128;
    const int tid = threadIdx.x, lane = tid & 31, warp = tid >> 5;
    const int wm = (warp >> 1) * 32, wn = (warp & 1) * 64;

    float acc[2][8][4];
#pragma unroll
    for (int a = 0; a < 2; a++)
#pragma unroll
        for (int b = 0; b < 8; b++)
#pragma unroll
            for (int c = 0; c < 4; c++) acc[a][b][c] = 0.f;

    // loader indexing: 1024 segments of 16B per operand per stage, 256 threads x 4
#define LOAD_STAGE(kt, s) do {                                                        \
        _Pragma("unroll")                                                             \
        for (int rep = 0; rep < 4; rep++) {                                           \
            const int gidx = rep * 256 + tid;                                         \
            const int row = gidx >> 3, c8 = gidx & 7;                                 \
            cp16(As[s] + row * LDS_ROW + c8 * 8,                                      \
                 g_x16 + (size_t)(bm + row) * IN_F + (kt) * BK + c8 * 8);             \
            cp16(Bs[s] + row * LDS_ROW + c8 * 8,                                      \
                 g_Ht + (size_t)(bn + row) * IN_F + (kt) * BK + c8 * 8);              \
        }                                                                             \
        asm volatile("cp.async.commit_group;\n" ::: "memory");                        \
    } while (0)

    LOAD_STAGE(0, 0);
    const int NK = IN_F / BK;   // 16
#pragma unroll 1
    for (int kt = 0; kt < NK; kt++) {
        const int s = kt & 1;
        if (kt + 1 < NK) {
            LOAD_STAGE(kt + 1, s ^ 1);
            asm volatile("cp.async.wait_group 1;\n" ::: "memory");
        } else {
            asm volatile("cp.async.wait_group 0;\n" ::: "memory");
        }
        __syncthreads();

#pragma unroll
        for (int ks = 0; ks < 4; ks++) {
            const int k0 = ks * 16;
            uint32_t af[2][4];
#pragma unroll
            for (int mi = 0; mi < 2; mi++)
                ldm4(af[mi], As[s] + (wm + mi * 16 + (lane & 15)) * LDS_ROW
                                   + k0 + ((lane >> 4) << 3));
            uint32_t bf[8][2];
#pragma unroll
            for (int nq = 0; nq < 4; nq++) {
                uint32_t r[4];
                ldm4(r, Bs[s] + (wn + nq * 16 + (lane & 15)) * LDS_ROW
                              + k0 + ((lane >> 4) << 3));
                bf[2 * nq][0]     = r[0]; bf[2 * nq][1]     = r[2];
                bf[2 * nq + 1][0] = r[1]; bf[2 * nq + 1][1] = r[3];
            }
#pragma unroll
            for (int mi = 0; mi < 2; mi++)
#pragma unroll
                for (int ni = 0; ni < 8; ni++)
                    mma16816(acc[mi][ni], af[mi], bf[ni]);
        }
        __syncthreads();   // compute on stage s done before it is reloaded at kt+2
    }
#undef LOAD_STAGE

    // epilogue: out = acc + bias[col]*corr[row]
    const int g = lane >> 2, t4 = lane & 3;
#pragma unroll
    for (int mi = 0; mi < 2; mi++) {
        const int r0 = bm + wm + mi * 16 + g;
        const float c0 = g_corr[r0], c1 = g_corr[r0 + 8];
#pragma unroll
        for (int ni = 0; ni < 8; ni++) {
            const int c = bn + wn + ni * 8 + 2 * t4;
            const float b0 = bias[c], b1 = bias[c + 1];
            float2 v0 = make_float2(acc[mi][ni][0] + b0 * c0, acc[mi][ni][1] + b1 * c0);
            float2 v1 = make_float2(acc[mi][ni][2] + b0 * c1, acc[mi][ni][3] + b1 * c1);
            *reinterpret_cast<float2*>(out + (size_t)r0 * OUT_F + c) = v0;
            *reinterpret_cast<float2*>(out + (size_t)(r0 + 8) * OUT_F + c) = v1;
        }
    }
}

// ---------------- launch ----------------
extern "C" void kernel_launch(void* const* d_in, const int* in_sizes, int n_in,
                              void* d_out, int out_size) {
    const float* x      = (const float*)d_in[0];   // [8192, 1024]
    const float* weight = (const float*)d_in[1];   // [1024, 1024]
    const float* bias   = (const float*)d_in[2];   // [1024]
    float* out = (float*)d_out;                    // [8192, 1024] fp32

    static bool attr_set = false;
    if (!attr_set) {
        cudaFuncSetAttribute(k_gemm, cudaFuncAttributeMaxDynamicSharedMemorySize, SMEM_DYN);
        attr_set = true;
    }

    k_init<<<IN_F / 256, 256>>>();
    k_minmax<<<256, 256>>>(weight, OUT_F * IN_F);
    k_build_ht<<<dim3(IN_F / 256, 8), 256>>>(weight);
    k_convert_corr<<<BATCH, 256>>>((const float4*)x);
    dim3 grid(OUT_F / 128, BATCH / 128);
    k_gemm<<<grid, 256, SMEM_DYN>>>(bias, out);
}

// round 7
// speedup vs baseline: 1.3545x; 1.3545x over previous
#include <cuda_runtime.h>
#include <cuda_fp16.h>
#include <cstdint>
#include <cstddef>

#define BATCH 8192
#define IN_F  1024
#define OUT_F 1024

// ---------------- scratch (static device globals; no allocation) ----------------
__device__ __align__(128) __half   g_x16[(size_t)BATCH * IN_F];  // fp16 x (16 MB)
__device__ __align__(128) __half   g_Ht[(size_t)OUT_F * IN_F];   // Ht[j][i] = H^T, [N][K] (2 MB)
__device__ __align__(16)  float    g_gbar[IN_F];                 // sum_j G_quant[i][j]
__device__ __align__(16)  float    g_geffbar[IN_F];              // sum_j G_eff[i][j]
__device__ float    g_corr[BATCH];
__device__ unsigned g_minmax[2];

// ---------------- small helpers ----------------
__device__ __forceinline__ unsigned fmap(float f) {
    unsigned u = __float_as_uint(f);
    return (u & 0x80000000u) ? ~u : (u | 0x80000000u);
}
__device__ __forceinline__ float funmap(unsigned m) {
    unsigned u = (m & 0x80000000u) ? (m ^ 0x80000000u) : ~m;
    return __uint_as_float(u);
}

__global__ void k_init() {
    int i = blockIdx.x * 256 + threadIdx.x;
    g_gbar[i] = 0.f;
    g_geffbar[i] = 0.f;
    if (i == 0) { g_minmax[0] = 0xFFFFFFFFu; g_minmax[1] = 0u; }
}

__global__ void k_minmax(const float* __restrict__ w, int n) {
    unsigned lmin = 0xFFFFFFFFu, lmax = 0u;
    for (int i = blockIdx.x * blockDim.x + threadIdx.x; i < n; i += gridDim.x * blockDim.x) {
        unsigned m = fmap(w[i]);
        lmin = min(lmin, m);
        lmax = max(lmax, m);
    }
#pragma unroll
    for (int o = 16; o; o >>= 1) {
        lmin = min(lmin, __shfl_xor_sync(0xFFFFFFFFu, lmin, o));
        lmax = max(lmax, __shfl_xor_sync(0xFFFFFFFFu, lmax, o));
    }
    __shared__ unsigned smin[8], smax[8];
    int warp = threadIdx.x >> 5;
    if ((threadIdx.x & 31) == 0) { smin[warp] = lmin; smax[warp] = lmax; }
    __syncthreads();
    if (threadIdx.x == 0) {
        unsigned a = smin[0], b = smax[0];
        for (int i = 1; i < 8; i++) { a = min(a, smin[i]); b = max(b, smax[i]); }
        atomicMin(&g_minmax[0], a);
        atomicMax(&g_minmax[1], b);
    }
}

// Build Ht[j][i] = ((G_eff - b)/a) in the SAME layout as weight (coalesced in i).
// Also accumulate per-i column sums of G_quant / G_eff (ratio of sums == ratio of means).
__global__ void k_build_ht(const float* __restrict__ w) {
    const int i  = blockIdx.x * 256 + threadIdx.x;   // input index (contiguous per warp)
    const int j0 = blockIdx.y * 128;                 // output-row chunk
    const float Wmin = funmap(g_minmax[0]);
    const float Wmax = funmap(g_minmax[1]);
    const float Ghrs = (float)(1.0 / 1000000.0);
    const float span = (float)(1.0 / 1000.0 - 1.0 / 1000000.0);
    const float step = (float)((1.0 / 1000.0 - 1.0 / 1000000.0) / 15.0);
    const float denomW = __fsub_rn(Wmax, Wmin);
    const float a      = __fdiv_rn(span, denomW);
    const float bconst = __fsub_rn(Ghrs, __fmul_rn(a, Wmin));
    const float rowterm = (float)(IN_F - i);

    float s_g = 0.f, s_e = 0.f;
#pragma unroll 4
    for (int jj = 0; jj < 128; jj++) {
        const int j = j0 + jj;
        float wv = w[(size_t)j * IN_F + i];
        float u  = __fdiv_rn(__fsub_rn(wv, Wmin), denomW);
        float G  = __fadd_rn(__fmul_rn(u, span), Ghrs);
        float q  = rintf(__fdiv_rn(__fsub_rn(G, Ghrs), step));
        float Gq = __fadd_rn(__fmul_rn(q, step), Ghrs);
        float rser = __fmul_rn(2.0f, __fadd_rn((float)(j + 1), rowterm));
        float Geff = __fdiv_rn(1.0f, __fadd_rn(__fdiv_rn(1.0f, Gq), rser));
        g_Ht[(size_t)j * IN_F + i] = __float2half_rn(__fdiv_rn(__fsub_rn(Geff, bconst), a));
        s_g += Gq;
        s_e += Geff;
    }
    atomicAdd(&g_gbar[i], s_g);
    atomicAdd(&g_geffbar[i], s_e);
}

// Warp-per-row: convert x -> fp16 and compute corr[b], warp-shuffle reduce only.
__global__ void k_convert_corr(const float4* __restrict__ x) {
    const int lane = threadIdx.x & 31;
    const int row  = blockIdx.x * 8 + (threadIdx.x >> 5);
    const float4* xr = x + (size_t)row * 256;
    __half2* dst = reinterpret_cast<__half2*>(g_x16 + (size_t)row * IN_F);
    const float4* ge4 = reinterpret_cast<const float4*>(g_geffbar);
    const float4* gb4 = reinterpret_cast<const float4*>(g_gbar);

    float num = 0.f, den = 0.f;
#pragma unroll
    for (int q = 0; q < 8; q++) {
        const int idx = lane + 32 * q;
        float4 v = xr[idx];
        dst[2 * idx]     = __floats2half2_rn(v.x, v.y);
        dst[2 * idx + 1] = __floats2half2_rn(v.z, v.w);
        float4 ge = ge4[idx], gb = gb4[idx];
        num += v.x * ge.x + v.y * ge.y + v.z * ge.z + v.w * ge.w;
        den += v.x * gb.x + v.y * gb.y + v.z * gb.z + v.w * gb.w;
    }
#pragma unroll
    for (int o = 16; o; o >>= 1) {
        num += __shfl_xor_sync(0xFFFFFFFFu, num, o);
        den += __shfl_xor_sync(0xFFFFFFFFu, den, o);
    }
    if (lane == 0) g_corr[row] = num / den;
}

// ========== fp16 mma.sync GEMM: out = x16 @ Ht^T + bias*corr ==========
// Structure identical to the proven 100.5us kernel (BM=BN=128, BK=32, 2-stage,
// static smem, 8 warps 4x2, warp tile 32x64). ONLY change: B comes from Ht[N][K]
// via non-trans ldmatrix (row padding 40 halfs -> conflict-free phases).

__device__ __forceinline__ void cp16(void* smem, const void* g) {
    unsigned s = (unsigned)__cvta_generic_to_shared(smem);
    asm volatile("cp.async.cg.shared.global [%0], [%1], 16;\n" :: "r"(s), "l"(g));
}
__device__ __forceinline__ void ldm4(uint32_t* r, const void* p) {
    unsigned a = (unsigned)__cvta_generic_to_shared(p);
    asm volatile("ldmatrix.sync.aligned.m8n8.x4.shared.b16 {%0,%1,%2,%3}, [%4];\n"
                 : "=r"(r[0]), "=r"(r[1]), "=r"(r[2]), "=r"(r[3]) : "r"(a));
}
__device__ __forceinline__ void mma16816(float* d, const uint32_t* a, const uint32_t* b) {
    asm volatile("mma.sync.aligned.m16n8k16.row.col.f32.f16.f16.f32 "
                 "{%0,%1,%2,%3}, {%4,%5,%6,%7}, {%8,%9}, {%0,%1,%2,%3};\n"
                 : "+f"(d[0]), "+f"(d[1]), "+f"(d[2]), "+f"(d[3])
                 : "r"(a[0]), "r"(a[1]), "r"(a[2]), "r"(a[3]), "r"(b[0]), "r"(b[1]));
}

__global__ __launch_bounds__(256, 2) void k_gemm(const float* __restrict__ bias,
                                                 float* __restrict__ out) {
    __shared__ __align__(16) __half As[2][128][40];   // M x K tile, +8 halfs pad
    __shared__ __align__(16) __half Bs[2][128][40];   // N x K tile, +8 halfs pad

    const int bm = blockIdx.y * 128, bn = blockIdx.x * 128;
    const int tid = threadIdx.x, lane = tid & 31, warp = tid >> 5;
    const int wm = (warp >> 1) * 32, wn = (warp & 1) * 64;

    float acc[2][8][4];
#pragma unroll
    for (int a = 0; a < 2; a++)
#pragma unroll
        for (int b = 0; b < 8; b++)
#pragma unroll
            for (int c = 0; c < 4; c++) acc[a][b][c] = 0.f;

    const int lrow = tid >> 2, lcol = (tid & 3) * 8;   // 64 rows/pass, 2 passes

#define LOAD_STAGE(kt, s) do {                                                              \
        cp16(&As[s][lrow][lcol],      g_x16 + (size_t)(bm + lrow) * IN_F + (kt) * 32 + lcol);        \
        cp16(&As[s][lrow + 64][lcol], g_x16 + (size_t)(bm + lrow + 64) * IN_F + (kt) * 32 + lcol);   \
        cp16(&Bs[s][lrow][lcol],      g_Ht + (size_t)(bn + lrow) * IN_F + (kt) * 32 + lcol);         \
        cp16(&Bs[s][lrow + 64][lcol], g_Ht + (size_t)(bn + lrow + 64) * IN_F + (kt) * 32 + lcol);    \
        asm volatile("cp.async.commit_group;\n" ::: "memory");                               \
    } while (0)

    LOAD_STAGE(0, 0);
    const int NK = IN_F / 32;   // 32 k-tiles
    for (int kt = 0; kt < NK; kt++) {
        const int s = kt & 1;
        if (kt + 1 < NK) {
            LOAD_STAGE(kt + 1, s ^ 1);
            asm volatile("cp.async.wait_group 1;\n" ::: "memory");
        } else {
            asm volatile("cp.async.wait_group 0;\n" ::: "memory");
        }
        __syncthreads();
#pragma unroll
        for (int ks = 0; ks < 2; ks++) {
            const int k0 = ks * 16;
            uint32_t af[2][4];
#pragma unroll
            for (int mi = 0; mi < 2; mi++)
                ldm4(af[mi], &As[s][wm + mi * 16 + (lane & 15)][k0 + ((lane >> 4) << 3)]);
            uint32_t bf[8][2];
#pragma unroll
            for (int nq = 0; nq < 4; nq++) {
                uint32_t r[4];
                ldm4(r, &Bs[s][wn + nq * 16 + (lane & 15)][k0 + ((lane >> 4) << 3)]);
                bf[2 * nq][0]     = r[0]; bf[2 * nq][1]     = r[2];
                bf[2 * nq + 1][0] = r[1]; bf[2 * nq + 1][1] = r[3];
            }
#pragma unroll
            for (int mi = 0; mi < 2; mi++)
#pragma unroll
                for (int ni = 0; ni < 8; ni++)
                    mma16816(acc[mi][ni], af[mi], bf[ni]);
        }
        __syncthreads();   // stage s fully consumed before it is reloaded at kt+2
    }
#undef LOAD_STAGE

    // epilogue: out = acc + bias[col]*corr[row]
    const int g = lane >> 2, t4 = lane & 3;
#pragma unroll
    for (int mi = 0; mi < 2; mi++) {
        const int r0 = bm + wm + mi * 16 + g;
        const float c0 = g_corr[r0], c1 = g_corr[r0 + 8];
#pragma unroll
        for (int ni = 0; ni < 8; ni++) {
            const int c = bn + wn + ni * 8 + 2 * t4;
            const float b0 = bias[c], b1 = bias[c + 1];
            float2 v0 = make_float2(acc[mi][ni][0] + b0 * c0, acc[mi][ni][1] + b1 * c0);
            float2 v1 = make_float2(acc[mi][ni][2] + b0 * c1, acc[mi][ni][3] + b1 * c1);
            *reinterpret_cast<float2*>(out + (size_t)r0 * OUT_F + c) = v0;
            *reinterpret_cast<float2*>(out + (size_t)(r0 + 8) * OUT_F + c) = v1;
        }
    }
}

// ---------------- launch ----------------
extern "C" void kernel_launch(void* const* d_in, const int* in_sizes, int n_in,
                              void* d_out, int out_size) {
    const float* x      = (const float*)d_in[0];   // [8192, 1024]
    const float* weight = (const float*)d_in[1];   // [1024, 1024]
    const float* bias   = (const float*)d_in[2];   // [1024]
    float* out = (float*)d_out;                    // [8192, 1024] fp32

    k_init<<<IN_F / 256, 256>>>();
    k_minmax<<<256, 256>>>(weight, OUT_F * IN_F);
    k_build_ht<<<dim3(IN_F / 256, 8), 256>>>(weight);
    k_convert_corr<<<BATCH / 8, 256>>>((const float4*)x);
    dim3 grid(OUT_F / 128, BATCH / 128);
    k_gemm<<<grid, 256>>>(bias, out);
}

// round 9
// speedup vs baseline: 2.0785x; 1.5346x over previous
#include <cuda_runtime.h>
#include <cuda_fp16.h>
#include <cstdint>
#include <cstddef>

#define BATCH 8192
#define IN_F  1024
#define OUT_F 1024

// ---------------- scratch (static device globals; no allocation) ----------------
__device__ __align__(128) __half   g_x16[(size_t)BATCH * IN_F];  // fp16 x (16 MB)
__device__ __align__(128) __half   g_H[(size_t)IN_F * OUT_F];    // H[i][j], [K][N] layout (2 MB)
__device__ __align__(16)  float    g_gbar[IN_F];                 // sum_j G_quant[i][j]
__device__ __align__(16)  float    g_geffbar[IN_F];              // sum_j G_eff[i][j]
__device__ float    g_corr[BATCH];
__device__ unsigned g_minmax[2];

// ---------------- small helpers ----------------
__device__ __forceinline__ unsigned fmap(float f) {
    unsigned u = __float_as_uint(f);
    return (u & 0x80000000u) ? ~u : (u | 0x80000000u);
}
__device__ __forceinline__ float funmap(unsigned m) {
    unsigned u = (m & 0x80000000u) ? (m ^ 0x80000000u) : ~m;
    return __uint_as_float(u);
}

__global__ void k_init() {
    int i = blockIdx.x * 256 + threadIdx.x;
    g_gbar[i] = 0.f;
    g_geffbar[i] = 0.f;
    if (i == 0) { g_minmax[0] = 0xFFFFFFFFu; g_minmax[1] = 0u; }
}

__global__ void k_minmax(const float* __restrict__ w, int n) {
    unsigned lmin = 0xFFFFFFFFu, lmax = 0u;
    for (int i = blockIdx.x * blockDim.x + threadIdx.x; i < n; i += gridDim.x * blockDim.x) {
        unsigned m = fmap(w[i]);
        lmin = min(lmin, m);
        lmax = max(lmax, m);
    }
#pragma unroll
    for (int o = 16; o; o >>= 1) {
        lmin = min(lmin, __shfl_xor_sync(0xFFFFFFFFu, lmin, o));
        lmax = max(lmax, __shfl_xor_sync(0xFFFFFFFFu, lmax, o));
    }
    __shared__ unsigned smin[8], smax[8];
    int warp = threadIdx.x >> 5;
    if ((threadIdx.x & 31) == 0) { smin[warp] = lmin; smax[warp] = lmax; }
    __syncthreads();
    if (threadIdx.x == 0) {
        unsigned a = smin[0], b = smax[0];
        for (int i = 1; i < 8; i++) { a = min(a, smin[i]); b = max(b, smax[i]); }
        atomicMin(&g_minmax[0], a);
        atomicMax(&g_minmax[1], b);
    }
}

// Build H[i][j] ([K][N] layout for the GEMM) with BOTH the weight read and the H
// write coalesced, via an smem transpose. Tile: 32 i x 128 j per block (32x8 threads).
// Also accumulates per-i sums of G_quant / G_eff (ratio of sums == ratio of means).
__global__ void k_build_h_t(const float* __restrict__ w) {
    __shared__ __half sT[128][33];          // [j-local][i-local], padded
    __shared__ float  sg[8][32], se[8][32];

    const int tx = threadIdx.x;             // i-local (0..31)
    const int ty = threadIdx.y;             // j-phase (0..7)
    const int i0 = blockIdx.x * 32, j0 = blockIdx.y * 128;
    const int i  = i0 + tx;

    const float Wmin = funmap(g_minmax[0]);
    const float Wmax = funmap(g_minmax[1]);
    const float Ghrs = (float)(1.0 / 1000000.0);
    const float span = (float)(1.0 / 1000.0 - 1.0 / 1000000.0);
    const float step = (float)((1.0 / 1000.0 - 1.0 / 1000000.0) / 15.0);
    const float denomW = __fsub_rn(Wmax, Wmin);
    const float a      = __fdiv_rn(span, denomW);
    const float bconst = __fsub_rn(Ghrs, __fmul_rn(a, Wmin));
    const float rowterm = (float)(IN_F - i);

    float s_g = 0.f, s_e = 0.f;
#pragma unroll 4
    for (int q = 0; q < 16; q++) {
        const int jl = ty + 8 * q;          // j-local
        const int j  = j0 + jl;
        float wv = w[(size_t)j * IN_F + i];                  // coalesced over tx
        float u  = __fdiv_rn(__fsub_rn(wv, Wmin), denomW);
        float G  = __fadd_rn(__fmul_rn(u, span), Ghrs);
        float qq = rintf(__fdiv_rn(__fsub_rn(G, Ghrs), step));
        float Gq = __fadd_rn(__fmul_rn(qq, step), Ghrs);
        float rser = __fmul_rn(2.0f, __fadd_rn((float)(j + 1), rowterm));
        float Geff = __fdiv_rn(1.0f, __fadd_rn(__fdiv_rn(1.0f, Gq), rser));
        sT[jl][tx] = __float2half_rn(__fdiv_rn(__fsub_rn(Geff, bconst), a));
        s_g += Gq;
        s_e += Geff;
    }
    sg[ty][tx] = s_g;
    se[ty][tx] = s_e;
    __syncthreads();

    if (ty == 0) {
        float ag = 0.f, ae = 0.f;
#pragma unroll
        for (int y = 0; y < 8; y++) { ag += sg[y][tx]; ae += se[y][tx]; }
        atomicAdd(&g_gbar[i], ag);
        atomicAdd(&g_geffbar[i], ae);
    }

    // write-out: H rows (fixed i), coalesced in j. 256 threads -> 32 rows x 8 chunks of 16 halfs
    const int tid = ty * 32 + tx;
    const int r = tid >> 3, c = tid & 7;    // r: i-local row, c: 16-half chunk
    __half* dst = g_H + (size_t)(i0 + r) * OUT_F + j0 + c * 16;
#pragma unroll
    for (int u = 0; u < 16; u++) dst[u] = sT[c * 16 + u][r];
}

// Warp-per-row: convert x -> fp16 and compute corr[b], warp-shuffle reduce only.
__global__ void k_convert_corr(const float4* __restrict__ x) {
    const int lane = threadIdx.x & 31;
    const int row  = blockIdx.x * 8 + (threadIdx.x >> 5);
    const float4* xr = x + (size_t)row * 256;
    __half2* dst = reinterpret_cast<__half2*>(g_x16 + (size_t)row * IN_F);
    const float4* ge4 = reinterpret_cast<const float4*>(g_geffbar);
    const float4* gb4 = reinterpret_cast<const float4*>(g_gbar);

    float num = 0.f, den = 0.f;
#pragma unroll
    for (int q = 0; q < 8; q++) {
        const int idx = lane + 32 * q;
        float4 v = xr[idx];
        dst[2 * idx]     = __floats2half2_rn(v.x, v.y);
        dst[2 * idx + 1] = __floats2half2_rn(v.z, v.w);
        float4 ge = ge4[idx], gb = gb4[idx];
        num += v.x * ge.x + v.y * ge.y + v.z * ge.z + v.w * ge.w;
        den += v.x * gb.x + v.y * gb.y + v.z * gb.z + v.w * gb.w;
    }
#pragma unroll
    for (int o = 16; o; o >>= 1) {
        num += __shfl_xor_sync(0xFFFFFFFFu, num, o);
        den += __shfl_xor_sync(0xFFFFFFFFu, den, o);
    }
    if (lane == 0) g_corr[row] = num / den;
}

// ========== fp16 mma.sync GEMM (VERBATIM R1 structure, measured ~76us) ==========
// out = x16 @ H + bias*corr.  A: [M][K] tile; B: H [K][N] tile, trans ldmatrix.
__device__ __forceinline__ void cp16(void* smem, const void* g) {
    unsigned s = (unsigned)__cvta_generic_to_shared(smem);
    asm volatile("cp.async.cg.shared.global [%0], [%1], 16;\n" :: "r"(s), "l"(g));
}
__device__ __forceinline__ void ldm_a(uint32_t* r, const void* p) {
    unsigned a = (unsigned)__cvta_generic_to_shared(p);
    asm volatile("ldmatrix.sync.aligned.m8n8.x4.shared.b16 {%0,%1,%2,%3}, [%4];\n"
                 : "=r"(r[0]), "=r"(r[1]), "=r"(r[2]), "=r"(r[3]) : "r"(a));
}
__device__ __forceinline__ void ldm_bt(uint32_t* r, const void* p) {
    unsigned a = (unsigned)__cvta_generic_to_shared(p);
    asm volatile("ldmatrix.sync.aligned.m8n8.x4.trans.shared.b16 {%0,%1,%2,%3}, [%4];\n"
                 : "=r"(r[0]), "=r"(r[1]), "=r"(r[2]), "=r"(r[3]) : "r"(a));
}
__device__ __forceinline__ void mma16816(float* d, const uint32_t* a, const uint32_t* b) {
    asm volatile("mma.sync.aligned.m16n8k16.row.col.f32.f16.f16.f32 "
                 "{%0,%1,%2,%3}, {%4,%5,%6,%7}, {%8,%9}, {%0,%1,%2,%3};\n"
                 : "+f"(d[0]), "+f"(d[1]), "+f"(d[2]), "+f"(d[3])
                 : "r"(a[0]), "r"(a[1]), "r"(a[2]), "r"(a[3]), "r"(b[0]), "r"(b[1]));
}

__global__ __launch_bounds__(256, 2) void k_gemm(const float* __restrict__ bias,
                                                 float* __restrict__ out) {
    __shared__ __align__(16) __half As[2][128][40];   // +8 halfs pad
    __shared__ __align__(16) __half Bs[2][32][136];

    const int bm = blockIdx.y * 128, bn = blockIdx.x * 128;
    const int tid = threadIdx.x, lane = tid & 31, warp = tid >> 5;
    const int wm = (warp >> 1) * 32, wn = (warp & 1) * 64;

    float acc[2][8][4];
#pragma unroll
    for (int a = 0; a < 2; a++)
#pragma unroll
        for (int b = 0; b < 8; b++)
#pragma unroll
            for (int c = 0; c < 4; c++) acc[a][b][c] = 0.f;

    const int arow = tid >> 2, acol = (tid & 3) * 8;   // A: 64 rows/pass, 2 passes
    const int brow = tid >> 4, bcol = (tid & 15) * 8;  // B: 16 rows/pass, 2 passes

#define LOAD_TILES(kt, s) do {                                                            \
        cp16(&As[s][arow][acol],      g_x16 + (size_t)(bm + arow) * IN_F + (kt) * 32 + acol);       \
        cp16(&As[s][arow + 64][acol], g_x16 + (size_t)(bm + arow + 64) * IN_F + (kt) * 32 + acol);  \
        cp16(&Bs[s][brow][bcol],      g_H + (size_t)((kt) * 32 + brow) * OUT_F + bn + bcol);        \
        cp16(&Bs[s][brow + 16][bcol], g_H + (size_t)((kt) * 32 + brow + 16) * OUT_F + bn + bcol);   \
        asm volatile("cp.async.commit_group;\n");                                          \
    } while (0)

    LOAD_TILES(0, 0);
    const int NK = IN_F / 32;   // 32 k-tiles
    for (int kt = 0; kt < NK; kt++) {
        const int s = kt & 1;
        if (kt + 1 < NK) {
            LOAD_TILES(kt + 1, s ^ 1);
            asm volatile("cp.async.wait_group 1;\n");
        } else {
            asm volatile("cp.async.wait_group 0;\n");
        }
        __syncthreads();
#pragma unroll
        for (int ks = 0; ks < 2; ks++) {
            const int k0 = ks * 16;
            uint32_t af[2][4];
#pragma unroll
            for (int mi = 0; mi < 2; mi++)
                ldm_a(af[mi], &As[s][wm + mi * 16 + (lane & 15)][k0 + ((lane >> 4) << 3)]);
            uint32_t bf[8][2];
#pragma unroll
            for (int nq = 0; nq < 4; nq++) {
                uint32_t r[4];
                ldm_bt(r, &Bs[s][k0 + (lane & 15)][wn + nq * 16 + ((lane & 16) >> 1)]);
                bf[2 * nq][0] = r[0]; bf[2 * nq][1] = r[1];
                bf[2 * nq + 1][0] = r[2]; bf[2 * nq + 1][1] = r[3];
            }
#pragma unroll
            for (int mi = 0; mi < 2; mi++)
#pragma unroll
                for (int ni = 0; ni < 8; ni++)
                    mma16816(acc[mi][ni], af[mi], bf[ni]);
        }
        __syncthreads();   // protect buffer s before it's overwritten two iterations later
    }
#undef LOAD_TILES

    // epilogue: out = acc + bias[col]*corr[row]
    const int g = lane >> 2, t = lane & 3;
#pragma unroll
    for (int mi = 0; mi < 2; mi++) {
        const int r0 = bm + wm + mi * 16 + g;
        const float c0 = g_corr[r0], c1 = g_corr[r0 + 8];
#pragma unroll
        for (int ni = 0; ni < 8; ni++) {
            const int c = bn + wn + ni * 8 + 2 * t;
            const float b0 = bias[c], b1 = bias[c + 1];
            float2 v0 = make_float2(acc[mi][ni][0] + b0 * c0, acc[mi][ni][1] + b1 * c0);
            float2 v1 = make_float2(acc[mi][ni][2] + b0 * c1, acc[mi][ni][3] + b1 * c1);
            *reinterpret_cast<float2*>(out + (size_t)r0 * OUT_F + c) = v0;
            *reinterpret_cast<float2*>(out + (size_t)(r0 + 8) * OUT_F + c) = v1;
        }
    }
}

// ---------------- launch ----------------
extern "C" void kernel_launch(void* const* d_in, const int* in_sizes, int n_in,
                              void* d_out, int out_size) {
    const float* x      = (const float*)d_in[0];   // [8192, 1024]
    const float* weight = (const float*)d_in[1];   // [1024, 1024]
    const float* bias   = (const float*)d_in[2];   // [1024]
    float* out = (float*)d_out;                    // [8192, 1024] fp32

    k_init<<<IN_F / 256, 256>>>();
    k_minmax<<<256, 256>>>(weight, OUT_F * IN_F);
    k_build_h_t<<<dim3(IN_F / 32, OUT_F / 128), dim3(32, 8)>>>(weight);
    k_convert_corr<<<BATCH / 8, 256>>>((const float4*)x);
    dim3 grid(OUT_F / 128, BATCH / 128);
    k_gemm<<<grid, 256>>>(bias, out);
}

// round 13
// speedup vs baseline: 2.4981x; 1.2019x over previous
#include <cuda_runtime.h>
#include <cuda_fp16.h>
#include <cstdint>
#include <cstddef>

#define BATCH 8192
#define IN_F  1024
#define OUT_F 1024

// ---------------- scratch (static device globals; no allocation) ----------------
__device__ __align__(128) __half   g_x16[(size_t)BATCH * IN_F];  // fp16 x (16 MB)
__device__ __align__(128) __half   g_H[(size_t)IN_F * OUT_F];    // H[i][j], [K][N] layout (2 MB)
__device__ __align__(16)  float    g_gbar[IN_F];                 // sum_j G_quant[i][j]
__device__ __align__(16)  float    g_geffbar[IN_F];              // sum_j G_eff[i][j]
__device__ float    g_corr[BATCH];
__device__ unsigned g_minmax[2];

// ---------------- small helpers ----------------
__device__ __forceinline__ unsigned fmap(float f) {
    unsigned u = __float_as_uint(f);
    return (u & 0x80000000u) ? ~u : (u | 0x80000000u);
}
__device__ __forceinline__ float funmap(unsigned m) {
    unsigned u = (m & 0x80000000u) ? (m ^ 0x80000000u) : ~m;
    return __uint_as_float(u);
}

__global__ void k_init() {
    int i = blockIdx.x * 256 + threadIdx.x;
    g_gbar[i] = 0.f;
    g_geffbar[i] = 0.f;
    if (i == 0) { g_minmax[0] = 0xFFFFFFFFu; g_minmax[1] = 0u; }
}

__global__ void k_minmax(const float* __restrict__ w, int n) {
    unsigned lmin = 0xFFFFFFFFu, lmax = 0u;
    for (int i = blockIdx.x * blockDim.x + threadIdx.x; i < n; i += gridDim.x * blockDim.x) {
        unsigned m = fmap(w[i]);
        lmin = min(lmin, m);
        lmax = max(lmax, m);
    }
#pragma unroll
    for (int o = 16; o; o >>= 1) {
        lmin = min(lmin, __shfl_xor_sync(0xFFFFFFFFu, lmin, o));
        lmax = max(lmax, __shfl_xor_sync(0xFFFFFFFFu, lmax, o));
    }
    __shared__ unsigned smin[8], smax[8];
    int warp = threadIdx.x >> 5;
    if ((threadIdx.x & 31) == 0) { smin[warp] = lmin; smax[warp] = lmax; }
    __syncthreads();
    if (threadIdx.x == 0) {
        unsigned a = smin[0], b = smax[0];
        for (int i = 1; i < 8; i++) { a = min(a, smin[i]); b = max(b, smax[i]); }
        atomicMin(&g_minmax[0], a);
        atomicMax(&g_minmax[1], b);
    }
}

// Build H[i][j] ([K][N] layout) with coalesced weight read AND coalesced H write
// via smem transpose. Also per-i sums of G_quant / G_eff.
__global__ void k_build_h_t(const float* __restrict__ w) {
    __shared__ __half sT[128][33];
    __shared__ float  sg[8][32], se[8][32];

    const int tx = threadIdx.x;             // i-local (0..31)
    const int ty = threadIdx.y;             // j-phase (0..7)
    const int i0 = blockIdx.x * 32, j0 = blockIdx.y * 128;
    const int i  = i0 + tx;

    const float Wmin = funmap(g_minmax[0]);
    const float Wmax = funmap(g_minmax[1]);
    const float Ghrs = (float)(1.0 / 1000000.0);
    const float span = (float)(1.0 / 1000.0 - 1.0 / 1000000.0);
    const float step = (float)((1.0 / 1000.0 - 1.0 / 1000000.0) / 15.0);
    const float denomW = __fsub_rn(Wmax, Wmin);
    const float a      = __fdiv_rn(span, denomW);
    const float bconst = __fsub_rn(Ghrs, __fmul_rn(a, Wmin));
    const float rowterm = (float)(IN_F - i);

    float s_g = 0.f, s_e = 0.f;
#pragma unroll 4
    for (int q = 0; q < 16; q++) {
        const int jl = ty + 8 * q;
        const int j  = j0 + jl;
        float wv = w[(size_t)j * IN_F + i];
        float u  = __fdiv_rn(__fsub_rn(wv, Wmin), denomW);
        float G  = __fadd_rn(__fmul_rn(u, span), Ghrs);
        float qq = rintf(__fdiv_rn(__fsub_rn(G, Ghrs), step));
        float Gq = __fadd_rn(__fmul_rn(qq, step), Ghrs);
        float rser = __fmul_rn(2.0f, __fadd_rn((float)(j + 1), rowterm));
        float Geff = __fdiv_rn(1.0f, __fadd_rn(__fdiv_rn(1.0f, Gq), rser));
        sT[jl][tx] = __float2half_rn(__fdiv_rn(__fsub_rn(Geff, bconst), a));
        s_g += Gq;
        s_e += Geff;
    }
    sg[ty][tx] = s_g;
    se[ty][tx] = s_e;
    __syncthreads();

    if (ty == 0) {
        float ag = 0.f, ae = 0.f;
#pragma unroll
        for (int y = 0; y < 8; y++) { ag += sg[y][tx]; ae += se[y][tx]; }
        atomicAdd(&g_gbar[i], ag);
        atomicAdd(&g_geffbar[i], ae);
    }

    const int tid = ty * 32 + tx;
    const int r = tid >> 3, c = tid & 7;
    __half* dst = g_H + (size_t)(i0 + r) * OUT_F + j0 + c * 16;
#pragma unroll
    for (int u = 0; u < 16; u++) dst[u] = sT[c * 16 + u][r];
}

// Warp-per-row: convert x -> fp16 (single 8B store per quad) + corr[b].
__global__ void k_convert_corr(const float4* __restrict__ x) {
    const int lane = threadIdx.x & 31;
    const int row  = blockIdx.x * 8 + (threadIdx.x >> 5);
    const float4* xr = x + (size_t)row * 256;
    __half2* dst2 = reinterpret_cast<__half2*>(g_x16 + (size_t)row * IN_F);
    const float4* ge4 = reinterpret_cast<const float4*>(g_geffbar);
    const float4* gb4 = reinterpret_cast<const float4*>(g_gbar);

    float num = 0.f, den = 0.f;
#pragma unroll
    for (int q = 0; q < 8; q++) {
        const int idx = lane + 32 * q;
        float4 v = xr[idx];
        __half2 pk[2];
        pk[0] = __floats2half2_rn(v.x, v.y);
        pk[1] = __floats2half2_rn(v.z, v.w);
        // single 8B store (dst2 + 2*idx is 8B-aligned)
        *reinterpret_cast<uint2*>(dst2 + 2 * idx) = *reinterpret_cast<const uint2*>(pk);
        float4 ge = ge4[idx], gb = gb4[idx];
        num += v.x * ge.x + v.y * ge.y + v.z * ge.z + v.w * ge.w;
        den += v.x * gb.x + v.y * gb.y + v.z * gb.z + v.w * gb.w;
    }
#pragma unroll
    for (int o = 16; o; o >>= 1) {
        num += __shfl_xor_sync(0xFFFFFFFFu, num, o);
        den += __shfl_xor_sync(0xFFFFFFFFu, den, o);
    }
    if (lane == 0) g_corr[row] = num / den;
}

// ========== fp16 mma.sync GEMM: out = x16 @ H + bias*corr ==========
// Proven R1 tiling (BM=BN=128, BK=32, trans-B). Change under test: 3-stage
// cp.async pipeline, ONE __syncthreads per k-tile (prefetch depth 2).
__device__ __forceinline__ void cp16(void* smem, const void* g) {
    unsigned s = (unsigned)__cvta_generic_to_shared(smem);
    asm volatile("cp.async.cg.shared.global [%0], [%1], 16;\n" :: "r"(s), "l"(g));
}
__device__ __forceinline__ void ldm_a(uint32_t* r, const void* p) {
    unsigned a = (unsigned)__cvta_generic_to_shared(p);
    asm volatile("ldmatrix.sync.aligned.m8n8.x4.shared.b16 {%0,%1,%2,%3}, [%4];\n"
                 : "=r"(r[0]), "=r"(r[1]), "=r"(r[2]), "=r"(r[3]) : "r"(a));
}
__device__ __forceinline__ void ldm_bt(uint32_t* r, const void* p) {
    unsigned a = (unsigned)__cvta_generic_to_shared(p);
    asm volatile("ldmatrix.sync.aligned.m8n8.x4.trans.shared.b16 {%0,%1,%2,%3}, [%4];\n"
                 : "=r"(r[0]), "=r"(r[1]), "=r"(r[2]), "=r"(r[3]) : "r"(a));
}
__device__ __forceinline__ void mma16816(float* d, const uint32_t* a, const uint32_t* b) {
    asm volatile("mma.sync.aligned.m16n8k16.row.col.f32.f16.f16.f32 "
                 "{%0,%1,%2,%3}, {%4,%5,%6,%7}, {%8,%9}, {%0,%1,%2,%3};\n"
                 : "+f"(d[0]), "+f"(d[1]), "+f"(d[2]), "+f"(d[3])
                 : "r"(a[0]), "r"(a[1]), "r"(a[2]), "r"(a[3]), "r"(b[0]), "r"(b[1]));
}

__global__ __launch_bounds__(256, 2) void k_gemm(const float* __restrict__ bias,
                                                 float* __restrict__ out) {
    __shared__ __align__(16) __half As[3][128][40];   // +8 halfs pad
    __shared__ __align__(16) __half Bs[3][32][136];

    const int bm = blockIdx.y * 128, bn = blockIdx.x * 128;
    const int tid = threadIdx.x, lane = tid & 31, warp = tid >> 5;
    const int wm = (warp >> 1) * 32, wn = (warp & 1) * 64;

    float acc[2][8][4];
#pragma unroll
    for (int a = 0; a < 2; a++)
#pragma unroll
        for (int b = 0; b < 8; b++)
#pragma unroll
            for (int c = 0; c < 4; c++) acc[a][b][c] = 0.f;

    const int arow = tid >> 2, acol = (tid & 3) * 8;   // A: 64 rows/pass, 2 passes
    const int brow = tid >> 4, bcol = (tid & 15) * 8;  // B: 16 rows/pass, 2 passes

#define LOAD_TILES(kt, s) do {                                                            \
        cp16(&As[s][arow][acol],      g_x16 + (size_t)(bm + arow) * IN_F + (kt) * 32 + acol);       \
        cp16(&As[s][arow + 64][acol], g_x16 + (size_t)(bm + arow + 64) * IN_F + (kt) * 32 + acol);  \
        cp16(&Bs[s][brow][bcol],      g_H + (size_t)((kt) * 32 + brow) * OUT_F + bn + bcol);        \
        cp16(&Bs[s][brow + 16][bcol], g_H + (size_t)((kt) * 32 + brow + 16) * OUT_F + bn + bcol);   \
        asm volatile("cp.async.commit_group;\n");                                          \
    } while (0)

    LOAD_TILES(0, 0);
    LOAD_TILES(1, 1);
    const int NK = IN_F / 32;   // 32 k-tiles
    for (int kt = 0; kt < NK; kt++) {
        const int s = kt % 3;
        if (kt + 1 < NK) asm volatile("cp.async.wait_group 1;\n");
        else             asm volatile("cp.async.wait_group 0;\n");
        __syncthreads();   // stage s ready; also fences last read of buffer (kt+2)%3 (read at kt-1)
#pragma unroll
        for (int ks = 0; ks < 2; ks++) {
            const int k0 = ks * 16;
            uint32_t af[2][4];
#pragma unroll
            for (int mi = 0; mi < 2; mi++)
                ldm_a(af[mi], &As[s][wm + mi * 16 + (lane & 15)][k0 + ((lane >> 4) << 3)]);
            uint32_t bf[8][2];
#pragma unroll
            for (int nq = 0; nq < 4; nq++) {
                uint32_t r[4];
                ldm_bt(r, &Bs[s][k0 + (lane & 15)][wn + nq * 16 + ((lane & 16) >> 1)]);
                bf[2 * nq][0] = r[0]; bf[2 * nq][1] = r[1];
                bf[2 * nq + 1][0] = r[2]; bf[2 * nq + 1][1] = r[3];
            }
#pragma unroll
            for (int mi = 0; mi < 2; mi++)
#pragma unroll
                for (int ni = 0; ni < 8; ni++)
                    mma16816(acc[mi][ni], af[mi], bf[ni]);
        }
        if (kt + 2 < NK) LOAD_TILES(kt + 2, (kt + 2) % 3);   // buffer last read at kt-1
    }
#undef LOAD_TILES

    // epilogue: out = acc + bias[col]*corr[row]
    const int g = lane >> 2, t = lane & 3;
#pragma unroll
    for (int mi = 0; mi < 2; mi++) {
        const int r0 = bm + wm + mi * 16 + g;
        const float c0 = g_corr[r0], c1 = g_corr[r0 + 8];
#pragma unroll
        for (int ni = 0; ni < 8; ni++) {
            const int c = bn + wn + ni * 8 + 2 * t;
            const float b0 = bias[c], b1 = bias[c + 1];
            float2 v0 = make_float2(acc[mi][ni][0] + b0 * c0, acc[mi][ni][1] + b1 * c0);
            float2 v1 = make_float2(acc[mi][ni][2] + b0 * c1, acc[mi][ni][3] + b1 * c1);
            *reinterpret_cast<float2*>(out + (size_t)r0 * OUT_F + c) = v0;
            *reinterpret_cast<float2*>(out + (size_t)(r0 + 8) * OUT_F + c) = v1;
        }
    }
}

// ---------------- launch ----------------
extern "C" void kernel_launch(void* const* d_in, const int* in_sizes, int n_in,
                              void* d_out, int out_size) {
    const float* x      = (const float*)d_in[0];   // [8192, 1024]
    const float* weight = (const float*)d_in[1];   // [1024, 1024]
    const float* bias   = (const float*)d_in[2];   // [1024]
    float* out = (float*)d_out;                    // [8192, 1024] fp32

    k_init<<<IN_F / 256, 256>>>();
    k_minmax<<<256, 256>>>(weight, OUT_F * IN_F);
    k_build_h_t<<<dim3(IN_F / 32, OUT_F / 128), dim3(32, 8)>>>(weight);
    k_convert_corr<<<BATCH / 8, 256>>>((const float4*)x);
    dim3 grid(OUT_F / 128, BATCH / 128);
    k_gemm<<<grid, 256>>>(bias, out);
}